// round 7
// baseline (speedup 1.0000x reference)
#include <cuda_runtime.h>
#include <cstdint>

// M=8192 rows, N=8192 cols, H=4096.
//   xf    = x * weight_scale[0] * activation_scale[row]
//   sw    = front * (back * sigmoid(back)),  s = sw * quant_scale[0]
//   scale = rowmax(|s|)/127;  i8 = clip(rint(s/scale), -128, 127)  (0 if scale<=0)
// Output (float32): [ i8 as float : M*H ][ scale : M ]
//
// One CTA per row, 256 threads, occ 8/SM. Warp absmax via redux.sync.max.u32,
// ONE barrier, every thread folds the 8 warp maxima from smem.
// R5 deltas vs R4: default-policy stores (let L2 buffer dirty output lines and
// drain in bursts instead of __stcs eager writeback), and clamp removed
// (|s*inv| <= 127*(1+1ulp) provably, rintf can't exceed the int8 range).
// Kernel is at the HBM/LTS mixed-stream floor; nothing on the SM side binds.

#define M_ROWS 8192
#define N_COLS 8192
#define H_COLS 4096
#define BLOCK_THREADS 256
#define N_WARPS (BLOCK_THREADS / 32)

__global__ __launch_bounds__(BLOCK_THREADS, 8)
void swiglu_quant_kernel(const float* __restrict__ x,
                         const float* __restrict__ weight_scale,
                         const float* __restrict__ activation_scale,
                         const float* __restrict__ quant_scale,
                         float* __restrict__ out) {
    const int row = blockIdx.x;
    const int tid = threadIdx.x;

    __shared__ float warp_max[N_WARPS];

    const float c = weight_scale[0] * activation_scale[row];
    const float q = quant_scale[0];

    const float4* __restrict__ pf =
        reinterpret_cast<const float4*>(x + (size_t)row * N_COLS) + tid;
    const float4* __restrict__ pb = pf + (H_COLS / 4);

    // ---- load (front-batched LDG.128s, streaming), SwiGLU, local absmax
    float4 f[4], b[4];
#pragma unroll
    for (int k = 0; k < 4; k++) {
        f[k] = __ldcs(pf + k * BLOCK_THREADS);
        b[k] = __ldcs(pb + k * BLOCK_THREADS);
    }

    float s[16];
    float amax = 0.0f;
#pragma unroll
    for (int k = 0; k < 4; k++) {
        const float fl[4] = {f[k].x, f[k].y, f[k].z, f[k].w};
        const float bk[4] = {b[k].x, b[k].y, b[k].z, b[k].w};
#pragma unroll
        for (int j = 0; j < 4; j++) {
            const float lin = fl[j] * c;
            const float g   = bk[j] * c;
            const float sig = 1.0f / (1.0f + __expf(-g));
            const float v   = lin * (g * sig) * q;
            s[k * 4 + j] = v;
            amax = fmaxf(amax, fabsf(v));
        }
    }

    // ---- absmax reduce: redux per warp, ONE barrier, every thread folds 8
    unsigned wmax = __reduce_max_sync(0xFFFFFFFFu, __float_as_uint(amax));
    if ((tid & 31) == 0) warp_max[tid >> 5] = __uint_as_float(wmax);
    __syncthreads();

    float m = warp_max[0];
#pragma unroll
    for (int w = 1; w < N_WARPS; w++) m = fmaxf(m, warp_max[w]);
    const float scale = m * (1.0f / 127.0f);
    const float inv   = (scale > 0.0f) ? (1.0f / scale) : 0.0f;

    // ---- quantize + default-policy stores (L2-buffered writeback)
    // No clamp needed: |s*inv| <= absmax*inv = 127*(1 +- 1ulp), so rintf
    // lands in [-127, 127] subset of the int8 range.
    float4* __restrict__ po =
        reinterpret_cast<float4*>(out + (size_t)row * H_COLS) + tid;
#pragma unroll
    for (int k = 0; k < 4; k++) {
        float4 o;
        o.x = rintf(s[k * 4 + 0] * inv);
        o.y = rintf(s[k * 4 + 1] * inv);
        o.z = rintf(s[k * 4 + 2] * inv);
        o.w = rintf(s[k * 4 + 3] * inv);
        po[k * BLOCK_THREADS] = o;
    }
    if (tid == 0) {
        out[(size_t)M_ROWS * H_COLS + row] = scale;
    }
}

extern "C" void kernel_launch(void* const* d_in, const int* in_sizes, int n_in,
                              void* d_out, int out_size) {
    const float* x  = (const float*)d_in[0];
    const float* ws = (const float*)d_in[1];
    const float* as = (const float*)d_in[2];
    const float* qs = (const float*)d_in[3];
    float* out = (float*)d_out;
    (void)in_sizes; (void)n_in; (void)out_size;

    swiglu_quant_kernel<<<M_ROWS, BLOCK_THREADS>>>(x, ws, as, qs, out);
}

// round 9
// speedup vs baseline: 1.0371x; 1.0371x over previous
#include <cuda_runtime.h>
#include <cstdint>

// M=8192 rows, N=8192 cols, H=4096.
//   xf    = x * weight_scale[0] * activation_scale[row]
//   sw    = front * (back * sigmoid(back)),  s = sw * quant_scale[0]
//   scale = rowmax(|s|)/127;  i8 = clip(rint(s/scale), -128, 127)  (0 if scale<=0)
// Output (float32): [ i8 as float : M*H ][ scale : M ]
//
// Final configuration (best of 6 measured variants):
//  - one CTA per row, 256 threads, occ 8/SM (best memory shape measured)
//  - front-batched __ldcs LDG.128 loads (streaming, evict-first)
//  - __stcs stores  (measured +2us vs default policy: keeps dirty output
//    lines from polluting L2 against the read stream)
//  - warp absmax via redux.sync.max.u32 (bit-monotone for nonneg floats),
//    ONE barrier, every thread folds the 8 warp maxima from smem
//  - no clamp: |s*inv| <= 127*(1+2ulp) provably, rintf lands in [-127,127]
// Kernel sits at the chip's mixed-stream memory floor (~6.1-6.4 TB/s eff).

#define M_ROWS 8192
#define N_COLS 8192
#define H_COLS 4096
#define BLOCK_THREADS 256
#define N_WARPS (BLOCK_THREADS / 32)

__global__ __launch_bounds__(BLOCK_THREADS, 8)
void swiglu_quant_kernel(const float* __restrict__ x,
                         const float* __restrict__ weight_scale,
                         const float* __restrict__ activation_scale,
                         const float* __restrict__ quant_scale,
                         float* __restrict__ out) {
    const int row = blockIdx.x;
    const int tid = threadIdx.x;

    __shared__ float warp_max[N_WARPS];

    const float c = weight_scale[0] * activation_scale[row];
    const float q = quant_scale[0];

    const float4* __restrict__ pf =
        reinterpret_cast<const float4*>(x + (size_t)row * N_COLS) + tid;
    const float4* __restrict__ pb = pf + (H_COLS / 4);

    // ---- load (front-batched LDG.128s, streaming), SwiGLU, local absmax
    float4 f[4], b[4];
#pragma unroll
    for (int k = 0; k < 4; k++) {
        f[k] = __ldcs(pf + k * BLOCK_THREADS);
        b[k] = __ldcs(pb + k * BLOCK_THREADS);
    }

    float s[16];
    float amax = 0.0f;
#pragma unroll
    for (int k = 0; k < 4; k++) {
        const float fl[4] = {f[k].x, f[k].y, f[k].z, f[k].w};
        const float bk[4] = {b[k].x, b[k].y, b[k].z, b[k].w};
#pragma unroll
        for (int j = 0; j < 4; j++) {
            const float lin = fl[j] * c;
            const float g   = bk[j] * c;
            const float sig = 1.0f / (1.0f + __expf(-g));
            const float v   = lin * (g * sig) * q;
            s[k * 4 + j] = v;
            amax = fmaxf(amax, fabsf(v));
        }
    }

    // ---- absmax reduce: redux per warp, ONE barrier, every thread folds 8
    unsigned wmax = __reduce_max_sync(0xFFFFFFFFu, __float_as_uint(amax));
    if ((tid & 31) == 0) warp_max[tid >> 5] = __uint_as_float(wmax);
    __syncthreads();

    float m = warp_max[0];
#pragma unroll
    for (int w = 1; w < N_WARPS; w++) m = fmaxf(m, warp_max[w]);
    const float scale = m * (1.0f / 127.0f);
    const float inv   = (scale > 0.0f) ? (1.0f / scale) : 0.0f;

    // ---- quantize + streaming stores (no clamp needed, see header)
    float4* __restrict__ po =
        reinterpret_cast<float4*>(out + (size_t)row * H_COLS) + tid;
#pragma unroll
    for (int k = 0; k < 4; k++) {
        float4 o;
        o.x = rintf(s[k * 4 + 0] * inv);
        o.y = rintf(s[k * 4 + 1] * inv);
        o.z = rintf(s[k * 4 + 2] * inv);
        o.w = rintf(s[k * 4 + 3] * inv);
        __stcs(po + k * BLOCK_THREADS, o);
    }
    if (tid == 0) {
        out[(size_t)M_ROWS * H_COLS + row] = scale;
    }
}

extern "C" void kernel_launch(void* const* d_in, const int* in_sizes, int n_in,
                              void* d_out, int out_size) {
    const float* x  = (const float*)d_in[0];
    const float* ws = (const float*)d_in[1];
    const float* as = (const float*)d_in[2];
    const float* qs = (const float*)d_in[3];
    float* out = (float*)d_out;
    (void)in_sizes; (void)n_in; (void)out_size;

    swiglu_quant_kernel<<<M_ROWS, BLOCK_THREADS>>>(x, ws, as, qs, out);
}

// round 11
// speedup vs baseline: 1.0376x; 1.0005x over previous
#include <cuda_runtime.h>
#include <cstdint>

// M=8192 rows, N=8192 cols, H=4096.
//   xf    = x * weight_scale[0] * activation_scale[row]
//   sw    = front * (back * sigmoid(back)),  s = sw * quant_scale[0]
//   scale = rowmax(|s|)/127;  i8 = clip(rint(s/scale), -128, 127)  (0 if scale<=0)
// Output (float32): [ i8 as float : M*H ][ scale : M ]
//
// Terminal configuration (8 measured variants):
//  - one CTA per row, 256 threads, occ 8/SM
//  - front-batched __ldcs LDG.128 loads (streaming, evict-first)
//  - __stcs stores (measured ~2us win vs default policy)
//  - warp absmax via redux.sync.max.u32, ONE barrier,
//    vectorized (2x LDS.128) fold of the 8 warp maxima
//  - no clamp: |s*inv| <= 127*(1+2ulp) provably, rintf in [-127,127]
// Kernel runs at the chip's mixed-stream memory floor:
// 390 MB / 60.5us = 6.45 TB/s effective == LTS path cap (~6300 B/cyc).

#define M_ROWS 8192
#define N_COLS 8192
#define H_COLS 4096
#define BLOCK_THREADS 256
#define N_WARPS (BLOCK_THREADS / 32)

__global__ __launch_bounds__(BLOCK_THREADS, 8)
void swiglu_quant_kernel(const float* __restrict__ x,
                         const float* __restrict__ weight_scale,
                         const float* __restrict__ activation_scale,
                         const float* __restrict__ quant_scale,
                         float* __restrict__ out) {
    const int row = blockIdx.x;
    const int tid = threadIdx.x;

    __shared__ __align__(16) float warp_max[N_WARPS];

    const float c = weight_scale[0] * activation_scale[row];
    const float q = quant_scale[0];

    const float4* __restrict__ pf =
        reinterpret_cast<const float4*>(x + (size_t)row * N_COLS) + tid;
    const float4* __restrict__ pb = pf + (H_COLS / 4);

    // ---- load (front-batched LDG.128s, streaming), SwiGLU, local absmax
    float4 f[4], b[4];
#pragma unroll
    for (int k = 0; k < 4; k++) {
        f[k] = __ldcs(pf + k * BLOCK_THREADS);
        b[k] = __ldcs(pb + k * BLOCK_THREADS);
    }

    float s[16];
    float amax = 0.0f;
#pragma unroll
    for (int k = 0; k < 4; k++) {
        const float fl[4] = {f[k].x, f[k].y, f[k].z, f[k].w};
        const float bk[4] = {b[k].x, b[k].y, b[k].z, b[k].w};
#pragma unroll
        for (int j = 0; j < 4; j++) {
            const float lin = fl[j] * c;
            const float g   = bk[j] * c;
            const float sig = 1.0f / (1.0f + __expf(-g));
            const float v   = lin * (g * sig) * q;
            s[k * 4 + j] = v;
            amax = fmaxf(amax, fabsf(v));
        }
    }

    // ---- absmax reduce: redux per warp, ONE barrier
    unsigned wmax = __reduce_max_sync(0xFFFFFFFFu, __float_as_uint(amax));
    if ((tid & 31) == 0) warp_max[tid >> 5] = __uint_as_float(wmax);
    __syncthreads();

    // vectorized fold: 2x LDS.128 + 7 max (vs 8 scalar LDS)
    const float4 w0 = reinterpret_cast<const float4*>(warp_max)[0];
    const float4 w1 = reinterpret_cast<const float4*>(warp_max)[1];
    float m = fmaxf(fmaxf(fmaxf(w0.x, w0.y), fmaxf(w0.z, w0.w)),
                    fmaxf(fmaxf(w1.x, w1.y), fmaxf(w1.z, w1.w)));
    const float scale = m * (1.0f / 127.0f);
    const float inv   = (scale > 0.0f) ? (1.0f / scale) : 0.0f;

    // scale store first: scattered 4B STG drains under the STG.128 burst
    if (tid == 0) {
        out[(size_t)M_ROWS * H_COLS + row] = scale;
    }

    // ---- quantize + streaming stores (no clamp needed, see header)
    float4* __restrict__ po =
        reinterpret_cast<float4*>(out + (size_t)row * H_COLS) + tid;
#pragma unroll
    for (int k = 0; k < 4; k++) {
        float4 o;
        o.x = rintf(s[k * 4 + 0] * inv);
        o.y = rintf(s[k * 4 + 1] * inv);
        o.z = rintf(s[k * 4 + 2] * inv);
        o.w = rintf(s[k * 4 + 3] * inv);
        __stcs(po + k * BLOCK_THREADS, o);
    }
}

extern "C" void kernel_launch(void* const* d_in, const int* in_sizes, int n_in,
                              void* d_out, int out_size) {
    const float* x  = (const float*)d_in[0];
    const float* ws = (const float*)d_in[1];
    const float* as = (const float*)d_in[2];
    const float* qs = (const float*)d_in[3];
    float* out = (float*)d_out;
    (void)in_sizes; (void)n_in; (void)out_size;

    swiglu_quant_kernel<<<M_ROWS, BLOCK_THREADS>>>(x, ws, as, qs, out);
}